// round 14
// baseline (speedup 1.0000x reference)
#include <cuda_runtime.h>
#include <math.h>

#define NB   32
#define NS   4096
#define ND   64
#define NL   13
#define NWR  13
#define NCLS 2
#define ROWS (NB*NS)          // 131072
#define SD   (NS*ND)          // 262144
#define VOCAB 512

__device__ float g_Vtab[VOCAB*ND];                  // [v][64]
__device__ float g_Ftab[(size_t)NWR*VOCAB*16];      // [k][v][16] (13 used)
__device__ float g_FgT[(size_t)NWR*NB*NL*NS];       // [k*NB+b][l][i]  88.6 MB
__device__ float g_Zdump[(size_t)ROWS*ND];          // fallback Z sink

__device__ __forceinline__ float gelu_exact(float x) {
    return 0.5f * x * (1.0f + erff(x * 0.7071067811865476f));
}

// ---------------------------------------------------------------------------
// tables_v: Vtab only. grid 32, block 256, 16 vocab rows/block.
// smem: Es(16x64) W1s(64x128) Hs(128x17) W2s(128x64) = 78 KB
// ---------------------------------------------------------------------------
__global__ __launch_bounds__(256) void tables_v_kernel(
    const float* __restrict__ emb,
    const float* __restrict__ vW1, const float* __restrict__ vb1,
    const float* __restrict__ vW2, const float* __restrict__ vb2) {
    extern __shared__ float sm[];
    float* Es  = sm;                    // 1024
    float* W1s = sm + 1024;             // 8192
    float* Hs  = sm + 9216;             // 2176
    float* W2s = sm + 11392;            // 8192

    const int v0 = blockIdx.x * 16;
    const int t  = threadIdx.x;

    for (int i = t; i < 1024; i += 256) Es[i] = emb[v0*64 + i];
    for (int i = t; i < 8192; i += 256) W1s[i] = vW1[i];
    for (int i = t; i < 8192; i += 256) W2s[i] = vW2[i];
    __syncthreads();

    {
        const int h  = t & 127;
        const int rg = t >> 7;
        const float b1 = vb1[h];
        float acc[8];
#pragma unroll
        for (int rr = 0; rr < 8; rr++) acc[rr] = 0.f;
#pragma unroll
        for (int dc = 0; dc < 4; dc++) {
            float w[16];
#pragma unroll
            for (int j = 0; j < 16; j++) w[j] = W1s[(dc*16 + j)*128 + h];
#pragma unroll
            for (int rr = 0; rr < 8; rr++) {
                const int r = rg*8 + rr;
                const float4* e4 = (const float4*)(Es + r*64 + dc*16);
#pragma unroll
                for (int j4 = 0; j4 < 4; j4++) {
                    float4 e = e4[j4];
                    acc[rr] = fmaf(e.x, w[4*j4+0], acc[rr]);
                    acc[rr] = fmaf(e.y, w[4*j4+1], acc[rr]);
                    acc[rr] = fmaf(e.z, w[4*j4+2], acc[rr]);
                    acc[rr] = fmaf(e.w, w[4*j4+3], acc[rr]);
                }
            }
        }
#pragma unroll
        for (int rr = 0; rr < 8; rr++)
            Hs[h*17 + rg*8 + rr] = gelu_exact(acc[rr] + b1);
    }
    __syncthreads();

    {
        const int d = t & 63, rgrp = t >> 6;
        float a[4];
#pragma unroll
        for (int rr = 0; rr < 4; rr++) a[rr] = vb2[d];
#pragma unroll 4
        for (int h2 = 0; h2 < 128; h2++) {
            const float wv = W2s[h2*64 + d];
#pragma unroll
            for (int rr = 0; rr < 4; rr++)
                a[rr] = fmaf(Hs[h2*17 + rgrp*4 + rr], wv, a[rr]);
        }
#pragma unroll
        for (int rr = 0; rr < 4; rr++)
            g_Vtab[(size_t)(v0 + rgrp*4 + rr)*64 + d] = a[rr];
    }
}

// ---------------------------------------------------------------------------
// tables_f: Ftab[k] for k = blockIdx.y. grid (32, 13), block 256.
// smem: Es(1024) W1s(8192) Hs(2176) W2s(1664) = 52 KB -> 4 CTAs/SM
// ---------------------------------------------------------------------------
__global__ __launch_bounds__(256) void tables_f_kernel(
    const float* __restrict__ emb,
    const float* __restrict__ fW1, const float* __restrict__ fb1,
    const float* __restrict__ fW2, const float* __restrict__ fb2) {
    extern __shared__ float sm[];
    float* Es  = sm;                    // 1024
    float* W1s = sm + 1024;             // 8192
    float* Hs  = sm + 9216;             // 2176
    float* W2s = sm + 11392;            // 1664

    const int k  = blockIdx.y;
    const int v0 = blockIdx.x * 16;
    const int t  = threadIdx.x;

    for (int i = t; i < 1024; i += 256) Es[i] = emb[v0*64 + i];
    const float* W1g = fW1 + (size_t)k*64*128;
    for (int i = t; i < 8192; i += 256) W1s[i] = W1g[i];
    const float* W2g = fW2 + (size_t)k*128*NL;
    for (int i = t; i < 128*NL; i += 256) W2s[i] = W2g[i];
    __syncthreads();

    {
        const int h  = t & 127;
        const int rg = t >> 7;
        const float b1 = fb1[k*128 + h];
        float acc[8];
#pragma unroll
        for (int rr = 0; rr < 8; rr++) acc[rr] = 0.f;
#pragma unroll
        for (int dc = 0; dc < 4; dc++) {
            float w[16];
#pragma unroll
            for (int j = 0; j < 16; j++) w[j] = W1s[(dc*16 + j)*128 + h];
#pragma unroll
            for (int rr = 0; rr < 8; rr++) {
                const int r = rg*8 + rr;
                const float4* e4 = (const float4*)(Es + r*64 + dc*16);
#pragma unroll
                for (int j4 = 0; j4 < 4; j4++) {
                    float4 e = e4[j4];
                    acc[rr] = fmaf(e.x, w[4*j4+0], acc[rr]);
                    acc[rr] = fmaf(e.y, w[4*j4+1], acc[rr]);
                    acc[rr] = fmaf(e.z, w[4*j4+2], acc[rr]);
                    acc[rr] = fmaf(e.w, w[4*j4+3], acc[rr]);
                }
            }
        }
#pragma unroll
        for (int rr = 0; rr < 8; rr++)
            Hs[h*17 + rg*8 + rr] = gelu_exact(acc[rr] + b1);
    }
    __syncthreads();

    if (t < 16*NL) {
        const int l = t >> 4, r = t & 15;
        float a0=0.f, a1=0.f, a2=0.f, a3=0.f;
#pragma unroll
        for (int h4 = 0; h4 < 32; h4++) {
            a0 = fmaf(Hs[(4*h4+0)*17 + r], W2s[(4*h4+0)*NL + l], a0);
            a1 = fmaf(Hs[(4*h4+1)*17 + r], W2s[(4*h4+1)*NL + l], a1);
            a2 = fmaf(Hs[(4*h4+2)*17 + r], W2s[(4*h4+2)*NL + l], a2);
            a3 = fmaf(Hs[(4*h4+3)*17 + r], W2s[(4*h4+3)*NL + l], a3);
        }
        g_Ftab[((size_t)k*VOCAB + v0 + r)*16 + l] = fb2[k*NL + l] + ((a0+a1)+(a2+a3));
    }
}

// ---------------------------------------------------------------------------
// Fused fgather + logits. Blocks [0, 6656): fgather; [6656, 7168): logits.
// ---------------------------------------------------------------------------
__global__ __launch_bounds__(256) void fgather_logits_kernel(
    const int* __restrict__ tok,
    const float* __restrict__ finW, const float* __restrict__ finb,
    float* __restrict__ out) {
    const int bx = blockIdx.x;
    const int t  = threadIdx.x;
    __shared__ float red[256];

    if (bx < 6656) {
        const int i  = (bx & 15) * 256 + t;
        const int kb = bx >> 4;          // k*NB + b
        const int k  = kb >> 5;
        const int b  = kb & 31;
        const int v  = tok[(size_t)b*NS + i];

        const float4* src = (const float4*)g_Ftab + ((size_t)k*VOCAB + v)*4;
        float4 q0 = src[0], q1 = src[1], q2 = src[2], q3 = src[3];
        const float f[13] = {q0.x,q0.y,q0.z,q0.w, q1.x,q1.y,q1.z,q1.w,
                             q2.x,q2.y,q2.z,q2.w, q3.x};
        float* dst = g_FgT + ((size_t)kb*NL)*NS + i;
#pragma unroll
        for (int l = 0; l < NL; l++) dst[(size_t)l*NS] = f[l];
    } else {
        const int lx = bx - 6656;
        const int s = lx & 7;
        const int c = (lx >> 3) & 1;
        const int b = lx >> 4;
        const int chunk = SD/4/8;   // 8192 float4

        const float4* Vt4 = (const float4*)g_Vtab;
        const float4* w   = (const float4*)(finW + (size_t)c*SD) + s*chunk;
        const int*    tkb = tok + (size_t)b*NS;

        float acc = 0.f;
        for (int i = t; i < chunk; i += 256) {
            int gi   = s*chunk + i;
            int srow = gi >> 4;
            int d4   = gi & 15;
            float4 vv = Vt4[tkb[srow]*16 + d4];
            float4 ww = w[i];
            acc = fmaf(vv.x, ww.x, acc);
            acc = fmaf(vv.y, ww.y, acc);
            acc = fmaf(vv.z, ww.z, acc);
            acc = fmaf(vv.w, ww.w, acc);
        }
        red[t] = acc;
        __syncthreads();
#pragma unroll
        for (int sft = 128; sft > 0; sft >>= 1) {
            if (t < sft) red[t] += red[t + sft];
            __syncthreads();
        }
        if (t == 0) atomicAdd(&out[b*NCLS + c], red[0] + (s == 0 ? finb[c] : 0.f));
    }
}

// ---------------------------------------------------------------------------
// Fused chord, all 13 rounds (R8/R12 structure, verbatim).
// ---------------------------------------------------------------------------
__global__ __launch_bounds__(1024, 1) void chord_all_kernel(
    const int* __restrict__ tok, float* __restrict__ outZ) {
    extern __shared__ float sm[];
    float4* Zs = (float4*)sm;            // [i], 64 KB
    float4* Vp = Zs + NS;                // [i], 64 KB

    const int b  = blockIdx.x >> 4;
    const int cp = blockIdx.x & 15;
    const int c0 = cp * 4;
    const int t  = threadIdx.x;

    float4 zreg[4];
    {
        const int* tkb = tok + (size_t)b*NS;
#pragma unroll
        for (int m = 0; m < 4; m++) {
            const int i = t + 1024*m;
            const int v = tkb[i];
            float4 a = *(const float4*)(g_Vtab + (size_t)v*64 + c0);
            Vp[i] = a;
            Zs[i] = a;
            zreg[m] = a;
        }
    }
    __syncthreads();

    float4 acc[4];
#pragma unroll 1
    for (int k = 0; k < NWR; k++) {
        const float* Fb = g_FgT + ((size_t)(k*NB + b)*NL)*NS + t;
#pragma unroll
        for (int m = 0; m < 4; m++) {
            const int i = t + 1024*m;
            const float* fp = Fb + 1024*m;
            const float f0  = fp[0];
            const float f1  = fp[(size_t)1*NS],  f2  = fp[(size_t)2*NS];
            const float f3  = fp[(size_t)3*NS],  f4  = fp[(size_t)4*NS];
            const float f5  = fp[(size_t)5*NS],  f6  = fp[(size_t)6*NS];
            const float f7  = fp[(size_t)7*NS],  f8  = fp[(size_t)8*NS];
            const float f9  = fp[(size_t)9*NS],  f10 = fp[(size_t)10*NS];
            const float f11 = fp[(size_t)11*NS], f12 = fp[(size_t)12*NS];

            float4 a = Vp[i];   // V residual

            const int m1 = (m+1)&3, m2 = (m+2)&3;
            a.x = fmaf(f0,  zreg[m ].x, a.x); a.y = fmaf(f0,  zreg[m ].y, a.y);
            a.z = fmaf(f0,  zreg[m ].z, a.z); a.w = fmaf(f0,  zreg[m ].w, a.w);
            a.x = fmaf(f11, zreg[m1].x, a.x); a.y = fmaf(f11, zreg[m1].y, a.y);
            a.z = fmaf(f11, zreg[m1].z, a.z); a.w = fmaf(f11, zreg[m1].w, a.w);
            a.x = fmaf(f12, zreg[m2].x, a.x); a.y = fmaf(f12, zreg[m2].y, a.y);
            a.z = fmaf(f12, zreg[m2].z, a.z); a.w = fmaf(f12, zreg[m2].w, a.w);

            const float fs[10] = {f1,f2,f3,f4,f5,f6,f7,f8,f9,f10};
            const int offs[10] = {1,2,4,8,16,32,64,128,256,512};
#pragma unroll
            for (int li = 0; li < 10; li++) {
                const int j = (i + offs[li]) & (NS-1);
                const float fl = fs[li];
                float4 z = Zs[j];
                a.x = fmaf(fl, z.x, a.x); a.y = fmaf(fl, z.y, a.y);
                a.z = fmaf(fl, z.z, a.z); a.w = fmaf(fl, z.w, a.w);
            }
            acc[m] = a;
        }
        __syncthreads();
#pragma unroll
        for (int m = 0; m < 4; m++) {
            zreg[m] = acc[m];
            Zs[t + 1024*m] = acc[m];
        }
        __syncthreads();
    }

#pragma unroll
    for (int m = 0; m < 4; m++) {
        const int i = t + 1024*m;
        *(float4*)(outZ + ((size_t)b*NS + i)*64 + c0) = zreg[m];
    }
}

// ---------------------------------------------------------------------------
extern "C" void kernel_launch(void* const* d_in, const int* in_sizes, int n_in,
                              void* d_out, int out_size) {
    const int*   tok  = (const int*)  d_in[0];
    const float* emb  = (const float*)d_in[1];
    const float* fW1  = (const float*)d_in[2];
    const float* fb1  = (const float*)d_in[3];
    const float* fW2  = (const float*)d_in[4];
    const float* fb2  = (const float*)d_in[5];
    const float* vW1  = (const float*)d_in[6];
    const float* vb1  = (const float*)d_in[7];
    const float* vW2  = (const float*)d_in[8];
    const float* vb2  = (const float*)d_in[9];
    const float* finW = (const float*)d_in[10];
    const float* finb = (const float*)d_in[11];
    float* out = (float*)d_out;

    const int tv_smem    = (1024 + 8192 + 2176 + 8192) * 4;   // 78336
    const int tf_smem    = (1024 + 8192 + 2176 + 1664) * 4;   // 52224 -> 4 CTAs/SM
    const int chord_smem = NS * 2 * 16;                       // 131072
    cudaFuncSetAttribute(tables_v_kernel, cudaFuncAttributeMaxDynamicSharedMemorySize, tv_smem);
    cudaFuncSetAttribute(tables_f_kernel, cudaFuncAttributeMaxDynamicSharedMemorySize, tf_smem);
    cudaFuncSetAttribute(chord_all_kernel, cudaFuncAttributeMaxDynamicSharedMemorySize, chord_smem);

    cudaMemsetAsync(out, 0, NB*NCLS*sizeof(float));

    dim3 fgrid(32, 13);
    tables_f_kernel<<<fgrid, 256, tf_smem>>>(emb, fW1, fb1, fW2, fb2);
    tables_v_kernel<<<32, 256, tv_smem>>>(emb, vW1, vb1, vW2, vb2);

    fgather_logits_kernel<<<6656 + 512, 256>>>(tok, finW, finb, out);

    float* zdst;
    if (out_size >= NB*NCLS + ROWS*ND) zdst = out + NB*NCLS;
    else cudaGetSymbolAddress((void**)&zdst, g_Zdump);
    chord_all_kernel<<<NB*16, 1024, chord_smem>>>(tok, zdst);
}

// round 15
// speedup vs baseline: 1.0351x; 1.0351x over previous
#include <cuda_runtime.h>
#include <math.h>

#define NB   32
#define NS   4096
#define ND   64
#define NL   13
#define NWR  13
#define NCLS 2
#define ROWS (NB*NS)          // 131072
#define SD   (NS*ND)          // 262144
#define VOCAB 512

__device__ float g_Vtab[VOCAB*ND];                  // [v][64]
__device__ float g_Ftab[(size_t)NWR*VOCAB*16];      // [k][v][16] (13 used)
__device__ float g_FgT[(size_t)NWR*NB*NL*NS];       // [k*NB+b][l][i]  88.6 MB
__device__ float g_Zdump[(size_t)ROWS*ND];          // fallback Z sink

__device__ __forceinline__ float gelu_exact(float x) {
    return 0.5f * x * (1.0f + erff(x * 0.7071067811865476f));
}

// ---------------------------------------------------------------------------
// Tables (R13 version): grid (32, 14), block 256. y==0 -> Vtab else Ftab[y-1].
// ---------------------------------------------------------------------------
__global__ __launch_bounds__(256) void tables_kernel(
    const float* __restrict__ emb,
    const float* __restrict__ fW1, const float* __restrict__ fb1,
    const float* __restrict__ fW2, const float* __restrict__ fb2,
    const float* __restrict__ vW1, const float* __restrict__ vb1,
    const float* __restrict__ vW2, const float* __restrict__ vb2) {
    extern __shared__ float sm[];
    float* Es  = sm;                    // 1024
    float* W1s = sm + 1024;             // 8192
    float* Hs  = sm + 9216;             // 2176
    float* W2s = sm + 11392;            // up to 8192

    const int y  = blockIdx.y;
    const int v0 = blockIdx.x * 16;
    const int t  = threadIdx.x;

    for (int i = t; i < 1024; i += 256) Es[i] = emb[v0*64 + i];
    const float* W1g = (y == 0) ? vW1 : fW1 + (size_t)(y-1)*64*128;
    for (int i = t; i < 8192; i += 256) W1s[i] = W1g[i];
    if (y == 0) {
        for (int i = t; i < 8192; i += 256) W2s[i] = vW2[i];
    } else {
        const float* W2g = fW2 + (size_t)(y-1)*128*NL;
        for (int i = t; i < 128*NL; i += 256) W2s[i] = W2g[i];
    }
    __syncthreads();

    {
        const int h  = t & 127;
        const int rg = t >> 7;
        const float b1 = (y == 0) ? vb1[h] : fb1[(y-1)*128 + h];
        float acc[8];
#pragma unroll
        for (int rr = 0; rr < 8; rr++) acc[rr] = 0.f;
#pragma unroll
        for (int dc = 0; dc < 4; dc++) {
            float w[16];
#pragma unroll
            for (int j = 0; j < 16; j++) w[j] = W1s[(dc*16 + j)*128 + h];
#pragma unroll
            for (int rr = 0; rr < 8; rr++) {
                const int r = rg*8 + rr;
                const float4* e4 = (const float4*)(Es + r*64 + dc*16);
#pragma unroll
                for (int j4 = 0; j4 < 4; j4++) {
                    float4 e = e4[j4];
                    acc[rr] = fmaf(e.x, w[4*j4+0], acc[rr]);
                    acc[rr] = fmaf(e.y, w[4*j4+1], acc[rr]);
                    acc[rr] = fmaf(e.z, w[4*j4+2], acc[rr]);
                    acc[rr] = fmaf(e.w, w[4*j4+3], acc[rr]);
                }
            }
        }
#pragma unroll
        for (int rr = 0; rr < 8; rr++)
            Hs[h*17 + rg*8 + rr] = gelu_exact(acc[rr] + b1);
    }
    __syncthreads();

    if (y == 0) {
        const int d = t & 63, rgrp = t >> 6;
        float a[4];
#pragma unroll
        for (int rr = 0; rr < 4; rr++) a[rr] = vb2[d];
#pragma unroll 4
        for (int h2 = 0; h2 < 128; h2++) {
            const float wv = W2s[h2*64 + d];
#pragma unroll
            for (int rr = 0; rr < 4; rr++)
                a[rr] = fmaf(Hs[h2*17 + rgrp*4 + rr], wv, a[rr]);
        }
#pragma unroll
        for (int rr = 0; rr < 4; rr++)
            g_Vtab[(size_t)(v0 + rgrp*4 + rr)*64 + d] = a[rr];
    } else {
        const int k = y - 1;
        if (t < 16*NL) {
            const int l = t >> 4, r = t & 15;
            float a0=0.f, a1=0.f, a2=0.f, a3=0.f;
#pragma unroll
            for (int h4 = 0; h4 < 32; h4++) {
                a0 = fmaf(Hs[(4*h4+0)*17 + r], W2s[(4*h4+0)*NL + l], a0);
                a1 = fmaf(Hs[(4*h4+1)*17 + r], W2s[(4*h4+1)*NL + l], a1);
                a2 = fmaf(Hs[(4*h4+2)*17 + r], W2s[(4*h4+2)*NL + l], a2);
                a3 = fmaf(Hs[(4*h4+3)*17 + r], W2s[(4*h4+3)*NL + l], a3);
            }
            g_Ftab[((size_t)k*VOCAB + v0 + r)*16 + l] = fb2[k*NL + l] + ((a0+a1)+(a2+a3));
        }
    }
}

// ---------------------------------------------------------------------------
// Fused fgather + logits. Blocks [0, 6656): fgather; [6656, 7168): logits.
// ---------------------------------------------------------------------------
__global__ __launch_bounds__(256) void fgather_logits_kernel(
    const int* __restrict__ tok,
    const float* __restrict__ finW, const float* __restrict__ finb,
    float* __restrict__ out) {
    const int bx = blockIdx.x;
    const int t  = threadIdx.x;
    __shared__ float red[256];

    if (bx < 6656) {
        const int i  = (bx & 15) * 256 + t;
        const int kb = bx >> 4;          // k*NB + b
        const int k  = kb >> 5;
        const int b  = kb & 31;
        const int v  = tok[(size_t)b*NS + i];

        const float4* src = (const float4*)g_Ftab + ((size_t)k*VOCAB + v)*4;
        float4 q0 = src[0], q1 = src[1], q2 = src[2], q3 = src[3];
        const float f[13] = {q0.x,q0.y,q0.z,q0.w, q1.x,q1.y,q1.z,q1.w,
                             q2.x,q2.y,q2.z,q2.w, q3.x};
        float* dst = g_FgT + ((size_t)kb*NL)*NS + i;
#pragma unroll
        for (int l = 0; l < NL; l++) dst[(size_t)l*NS] = f[l];
    } else {
        const int lx = bx - 6656;
        const int s = lx & 7;
        const int c = (lx >> 3) & 1;
        const int b = lx >> 4;
        const int chunk = SD/4/8;   // 8192 float4

        const float4* Vt4 = (const float4*)g_Vtab;
        const float4* w   = (const float4*)(finW + (size_t)c*SD) + s*chunk;
        const int*    tkb = tok + (size_t)b*NS;

        float acc = 0.f;
        for (int i = t; i < chunk; i += 256) {
            int gi   = s*chunk + i;
            int srow = gi >> 4;
            int d4   = gi & 15;
            float4 vv = Vt4[tkb[srow]*16 + d4];
            float4 ww = w[i];
            acc = fmaf(vv.x, ww.x, acc);
            acc = fmaf(vv.y, ww.y, acc);
            acc = fmaf(vv.z, ww.z, acc);
            acc = fmaf(vv.w, ww.w, acc);
        }
        red[t] = acc;
        __syncthreads();
#pragma unroll
        for (int sft = 128; sft > 0; sft >>= 1) {
            if (t < sft) red[t] += red[t + sft];
            __syncthreads();
        }
        if (t == 0) atomicAdd(&out[b*NCLS + c], red[0] + (s == 0 ? finb[c] : 0.f));
    }
}

// ---------------------------------------------------------------------------
// Fused chord, all 13 rounds. Block = (b, cp 0..15) -> 4 cols c0=cp*4.
// 1024 threads; thread t owns i = t + 1024m (m=0..3).
// Ping-pong Z planes, ONE sync per round, immediate per-m writeback.
// V residual held in REGISTERS (vreg) -> no V smem plane, -16 wf/warp/round.
// Links 0/1024/2048 from zreg (with stash for overwritten entries);
// links 1..512 from the read plane. F from g_FgT (coalesced scalar LDG).
// ---------------------------------------------------------------------------
__global__ __launch_bounds__(1024, 1) void chord_all_kernel(
    const int* __restrict__ tok, float* __restrict__ outZ) {
    extern __shared__ float sm[];
    float4* Z0 = (float4*)sm;            // [i], 64 KB
    float4* Z1 = Z0 + NS;                // [i], 64 KB

    const int b  = blockIdx.x >> 4;
    const int cp = blockIdx.x & 15;
    const int c0 = cp * 4;
    const int t  = threadIdx.x;

    float4 zreg[4], vreg[4];
    {
        const int* tkb = tok + (size_t)b*NS;
#pragma unroll
        for (int m = 0; m < 4; m++) {
            const int i = t + 1024*m;
            const int v = tkb[i];
            float4 a = *(const float4*)(g_Vtab + (size_t)v*64 + c0);
            vreg[m] = a;
            zreg[m] = a;
            Z0[i] = a;
        }
    }
    __syncthreads();

#pragma unroll 1
    for (int k = 0; k < NWR; k++) {
        const float4* Zr = (k & 1) ? Z1 : Z0;
        float4*       Zw = (k & 1) ? Z0 : Z1;
        const float* Fb = g_FgT + ((size_t)(k*NB + b)*NL)*NS + t;
        // stash old zreg values overwritten before later m's consume them
        const float4 st0 = zreg[0], st1 = zreg[1];
#pragma unroll
        for (int m = 0; m < 4; m++) {
            const int i = t + 1024*m;
            const float* fp = Fb + 1024*m;
            const float f0  = fp[0];
            const float f1  = fp[(size_t)1*NS],  f2  = fp[(size_t)2*NS];
            const float f3  = fp[(size_t)3*NS],  f4  = fp[(size_t)4*NS];
            const float f5  = fp[(size_t)5*NS],  f6  = fp[(size_t)6*NS];
            const float f7  = fp[(size_t)7*NS],  f8  = fp[(size_t)8*NS];
            const float f9  = fp[(size_t)9*NS],  f10 = fp[(size_t)10*NS];
            const float f11 = fp[(size_t)11*NS], f12 = fp[(size_t)12*NS];

            float4 a = vreg[m];   // V residual from registers

            // register links: off 0 (f0) -> m, 1024 (f11) -> m+1, 2048 (f12) -> m+2
            const float4 zm  = zreg[m];
            const float4 zm1 = (m == 3) ? st0 : zreg[(m+1)&3];
            const float4 zm2 = (m == 2) ? st0 : ((m == 3) ? st1 : zreg[(m+2)&3]);
            a.x = fmaf(f0,  zm.x,  a.x); a.y = fmaf(f0,  zm.y,  a.y);
            a.z = fmaf(f0,  zm.z,  a.z); a.w = fmaf(f0,  zm.w,  a.w);
            a.x = fmaf(f11, zm1.x, a.x); a.y = fmaf(f11, zm1.y, a.y);
            a.z = fmaf(f11, zm1.z, a.z); a.w = fmaf(f11, zm1.w, a.w);
            a.x = fmaf(f12, zm2.x, a.x); a.y = fmaf(f12, zm2.y, a.y);
            a.z = fmaf(f12, zm2.z, a.z); a.w = fmaf(f12, zm2.w, a.w);

            // smem links: off 1..512 (f1..f10) from the read plane
            const float fs[10] = {f1,f2,f3,f4,f5,f6,f7,f8,f9,f10};
            const int offs[10] = {1,2,4,8,16,32,64,128,256,512};
#pragma unroll
            for (int li = 0; li < 10; li++) {
                const int j = (i + offs[li]) & (NS-1);
                const float fl = fs[li];
                float4 z = Zr[j];
                a.x = fmaf(fl, z.x, a.x); a.y = fmaf(fl, z.y, a.y);
                a.z = fmaf(fl, z.z, a.z); a.w = fmaf(fl, z.w, a.w);
            }

            // immediate writeback (no WAR: write plane != read plane)
            Zw[i] = a;
            zreg[m] = a;
        }
        __syncthreads();
    }

    // final Z (in zreg) -> gmem
#pragma unroll
    for (int m = 0; m < 4; m++) {
        const int i = t + 1024*m;
        *(float4*)(outZ + ((size_t)b*NS + i)*64 + c0) = zreg[m];
    }
}

// ---------------------------------------------------------------------------
extern "C" void kernel_launch(void* const* d_in, const int* in_sizes, int n_in,
                              void* d_out, int out_size) {
    const int*   tok  = (const int*)  d_in[0];
    const float* emb  = (const float*)d_in[1];
    const float* fW1  = (const float*)d_in[2];
    const float* fb1  = (const float*)d_in[3];
    const float* fW2  = (const float*)d_in[4];
    const float* fb2  = (const float*)d_in[5];
    const float* vW1  = (const float*)d_in[6];
    const float* vb1  = (const float*)d_in[7];
    const float* vW2  = (const float*)d_in[8];
    const float* vb2  = (const float*)d_in[9];
    const float* finW = (const float*)d_in[10];
    const float* finb = (const float*)d_in[11];
    float* out = (float*)d_out;

    const int tables_smem = (1024 + 8192 + 2176 + 8192) * 4;   // 78336
    const int chord_smem  = NS * 2 * 16;                       // 131072
    cudaFuncSetAttribute(tables_kernel,    cudaFuncAttributeMaxDynamicSharedMemorySize, tables_smem);
    cudaFuncSetAttribute(chord_all_kernel, cudaFuncAttributeMaxDynamicSharedMemorySize, chord_smem);

    cudaMemsetAsync(out, 0, NB*NCLS*sizeof(float));

    dim3 tgrid(32, 14);
    tables_kernel<<<tgrid, 256, tables_smem>>>(emb, fW1, fb1, fW2, fb2,
                                               vW1, vb1, vW2, vb2);

    fgather_logits_kernel<<<6656 + 512, 256>>>(tok, finW, finb, out);

    float* zdst;
    if (out_size >= NB*NCLS + ROWS*ND) zdst = out + NB*NCLS;
    else cudaGetSymbolAddress((void**)&zdst, g_Zdump);
    chord_all_kernel<<<NB*16, 1024, chord_smem>>>(tok, zdst);
}

// round 16
// speedup vs baseline: 1.0620x; 1.0259x over previous
#include <cuda_runtime.h>
#include <math.h>

#define NB   32
#define NS   4096
#define ND   64
#define NL   13
#define NWR  13
#define NCLS 2
#define ROWS (NB*NS)          // 131072
#define SD   (NS*ND)          // 262144
#define VOCAB 512

__device__ float g_Vtab[VOCAB*ND];                  // [v][64]
__device__ float g_Ftab[(size_t)NWR*VOCAB*16];      // [k][v][16] (13 used)
__device__ float g_FgT[(size_t)NWR*NB*NL*NS];       // [k*NB+b][l][i]  88.6 MB
__device__ float g_Zdump[(size_t)ROWS*ND];          // fallback Z sink

__device__ __forceinline__ float gelu_exact(float x) {
    return 0.5f * x * (1.0f + erff(x * 0.7071067811865476f));
}

// ---------------------------------------------------------------------------
// Tables: grid (32, 14), block 256. y==0 -> Vtab else Ftab[y-1].
// float4 staging for Es/W1s/W2s.
// ---------------------------------------------------------------------------
__global__ __launch_bounds__(256) void tables_kernel(
    const float* __restrict__ emb,
    const float* __restrict__ fW1, const float* __restrict__ fb1,
    const float* __restrict__ fW2, const float* __restrict__ fb2,
    const float* __restrict__ vW1, const float* __restrict__ vb1,
    const float* __restrict__ vW2, const float* __restrict__ vb2) {
    extern __shared__ float sm[];
    float* Es  = sm;                    // 1024
    float* W1s = sm + 1024;             // 8192
    float* Hs  = sm + 9216;             // 2176
    float* W2s = sm + 11392;            // up to 8192

    const int y  = blockIdx.y;
    const int v0 = blockIdx.x * 16;
    const int t  = threadIdx.x;

    // float4 staging
    {
        float4*       Es4 = (float4*)Es;
        const float4* eg  = (const float4*)(emb + v0*64);
        if (t < 256) Es4[t] = eg[t];
        float4*       W14 = (float4*)W1s;
        const float4* w1g = (const float4*)((y == 0) ? vW1 : fW1 + (size_t)(y-1)*64*128);
#pragma unroll
        for (int i = 0; i < 8; i++) W14[t + 256*i] = w1g[t + 256*i];
        if (y == 0) {
            float4*       W24 = (float4*)W2s;
            const float4* w2g = (const float4*)vW2;
#pragma unroll
            for (int i = 0; i < 8; i++) W24[t + 256*i] = w2g[t + 256*i];
        } else {
            const float* W2g = fW2 + (size_t)(y-1)*128*NL;
            for (int i = t; i < 128*NL; i += 256) W2s[i] = W2g[i];
        }
    }
    __syncthreads();

    {
        const int h  = t & 127;
        const int rg = t >> 7;
        const float b1 = (y == 0) ? vb1[h] : fb1[(y-1)*128 + h];
        float acc[8];
#pragma unroll
        for (int rr = 0; rr < 8; rr++) acc[rr] = 0.f;
#pragma unroll
        for (int dc = 0; dc < 4; dc++) {
            float w[16];
#pragma unroll
            for (int j = 0; j < 16; j++) w[j] = W1s[(dc*16 + j)*128 + h];
#pragma unroll
            for (int rr = 0; rr < 8; rr++) {
                const int r = rg*8 + rr;
                const float4* e4 = (const float4*)(Es + r*64 + dc*16);
#pragma unroll
                for (int j4 = 0; j4 < 4; j4++) {
                    float4 e = e4[j4];
                    acc[rr] = fmaf(e.x, w[4*j4+0], acc[rr]);
                    acc[rr] = fmaf(e.y, w[4*j4+1], acc[rr]);
                    acc[rr] = fmaf(e.z, w[4*j4+2], acc[rr]);
                    acc[rr] = fmaf(e.w, w[4*j4+3], acc[rr]);
                }
            }
        }
#pragma unroll
        for (int rr = 0; rr < 8; rr++)
            Hs[h*17 + rg*8 + rr] = gelu_exact(acc[rr] + b1);
    }
    __syncthreads();

    if (y == 0) {
        const int d = t & 63, rgrp = t >> 6;
        float a[4];
#pragma unroll
        for (int rr = 0; rr < 4; rr++) a[rr] = vb2[d];
#pragma unroll 4
        for (int h2 = 0; h2 < 128; h2++) {
            const float wv = W2s[h2*64 + d];
#pragma unroll
            for (int rr = 0; rr < 4; rr++)
                a[rr] = fmaf(Hs[h2*17 + rgrp*4 + rr], wv, a[rr]);
        }
#pragma unroll
        for (int rr = 0; rr < 4; rr++)
            g_Vtab[(size_t)(v0 + rgrp*4 + rr)*64 + d] = a[rr];
    } else {
        const int k = y - 1;
        if (t < 16*NL) {
            const int l = t >> 4, r = t & 15;
            float a0=0.f, a1=0.f, a2=0.f, a3=0.f;
#pragma unroll
            for (int h4 = 0; h4 < 32; h4++) {
                a0 = fmaf(Hs[(4*h4+0)*17 + r], W2s[(4*h4+0)*NL + l], a0);
                a1 = fmaf(Hs[(4*h4+1)*17 + r], W2s[(4*h4+1)*NL + l], a1);
                a2 = fmaf(Hs[(4*h4+2)*17 + r], W2s[(4*h4+2)*NL + l], a2);
                a3 = fmaf(Hs[(4*h4+3)*17 + r], W2s[(4*h4+3)*NL + l], a3);
            }
            g_Ftab[((size_t)k*VOCAB + v0 + r)*16 + l] = fb2[k*NL + l] + ((a0+a1)+(a2+a3));
        }
    }
}

// ---------------------------------------------------------------------------
// Fused fgather + logits. Blocks [0, 3328): fgather (2 rows/thread);
// blocks [3328, 3840): logits.
// ---------------------------------------------------------------------------
__global__ __launch_bounds__(256) void fgather_logits_kernel(
    const int* __restrict__ tok,
    const float* __restrict__ finW, const float* __restrict__ finb,
    float* __restrict__ out) {
    const int bx = blockIdx.x;
    const int t  = threadIdx.x;
    __shared__ float red[256];

    if (bx < 3328) {
        // fgather: FgT[(k*NB+b)*13 + l][i] = Ftab[k][tok[b][i]][l], 2 i/thread
        const int kb = bx >> 3;          // k*NB + b
        const int k  = kb >> 5;
        const int b  = kb & 31;
        const int i0 = (bx & 7) * 512 + t;

        const float4* Ft4 = (const float4*)g_Ftab + (size_t)k*VOCAB*4;
        float* dst = g_FgT + ((size_t)kb*NL)*NS;
        const int* tkb = tok + (size_t)b*NS;

        const int ia = i0, ib = i0 + 256;
        const int va = tkb[ia], vb = tkb[ib];
        float4 a0 = Ft4[va*4], a1 = Ft4[va*4+1], a2 = Ft4[va*4+2], a3 = Ft4[va*4+3];
        float4 b0 = Ft4[vb*4], b1 = Ft4[vb*4+1], b2 = Ft4[vb*4+2], b3 = Ft4[vb*4+3];
        const float fa[13] = {a0.x,a0.y,a0.z,a0.w, a1.x,a1.y,a1.z,a1.w,
                              a2.x,a2.y,a2.z,a2.w, a3.x};
        const float fb[13] = {b0.x,b0.y,b0.z,b0.w, b1.x,b1.y,b1.z,b1.w,
                              b2.x,b2.y,b2.z,b2.w, b3.x};
#pragma unroll
        for (int l = 0; l < NL; l++) {
            dst[(size_t)l*NS + ia] = fa[l];
            dst[(size_t)l*NS + ib] = fb[l];
        }
    } else {
        const int lx = bx - 3328;
        const int s = lx & 7;
        const int c = (lx >> 3) & 1;
        const int b = lx >> 4;
        const int chunk = SD/4/8;   // 8192 float4

        const float4* Vt4 = (const float4*)g_Vtab;
        const float4* w   = (const float4*)(finW + (size_t)c*SD) + s*chunk;
        const int*    tkb = tok + (size_t)b*NS;

        float acc = 0.f;
        for (int i = t; i < chunk; i += 256) {
            int gi   = s*chunk + i;
            int srow = gi >> 4;
            int d4   = gi & 15;
            float4 vv = Vt4[tkb[srow]*16 + d4];
            float4 ww = w[i];
            acc = fmaf(vv.x, ww.x, acc);
            acc = fmaf(vv.y, ww.y, acc);
            acc = fmaf(vv.z, ww.z, acc);
            acc = fmaf(vv.w, ww.w, acc);
        }
        red[t] = acc;
        __syncthreads();
#pragma unroll
        for (int sft = 128; sft > 0; sft >>= 1) {
            if (t < sft) red[t] += red[t + sft];
            __syncthreads();
        }
        if (t == 0) atomicAdd(&out[b*NCLS + c], red[0] + (s == 0 ? finb[c] : 0.f));
    }
}

// ---------------------------------------------------------------------------
// Fused chord (R15, verbatim): ping-pong Z planes, vreg residual,
// one sync/round. Block = (b, cp 0..15), 1024 threads, i = t + 1024m.
// ---------------------------------------------------------------------------
__global__ __launch_bounds__(1024, 1) void chord_all_kernel(
    const int* __restrict__ tok, float* __restrict__ outZ) {
    extern __shared__ float sm[];
    float4* Z0 = (float4*)sm;            // [i], 64 KB
    float4* Z1 = Z0 + NS;                // [i], 64 KB

    const int b  = blockIdx.x >> 4;
    const int cp = blockIdx.x & 15;
    const int c0 = cp * 4;
    const int t  = threadIdx.x;

    float4 zreg[4], vreg[4];
    {
        const int* tkb = tok + (size_t)b*NS;
#pragma unroll
        for (int m = 0; m < 4; m++) {
            const int i = t + 1024*m;
            const int v = tkb[i];
            float4 a = *(const float4*)(g_Vtab + (size_t)v*64 + c0);
            vreg[m] = a;
            zreg[m] = a;
            Z0[i] = a;
        }
    }
    __syncthreads();

#pragma unroll 1
    for (int k = 0; k < NWR; k++) {
        const float4* Zr = (k & 1) ? Z1 : Z0;
        float4*       Zw = (k & 1) ? Z0 : Z1;
        const float* Fb = g_FgT + ((size_t)(k*NB + b)*NL)*NS + t;
        const float4 st0 = zreg[0], st1 = zreg[1];
#pragma unroll
        for (int m = 0; m < 4; m++) {
            const int i = t + 1024*m;
            const float* fp = Fb + 1024*m;
            const float f0  = fp[0];
            const float f1  = fp[(size_t)1*NS],  f2  = fp[(size_t)2*NS];
            const float f3  = fp[(size_t)3*NS],  f4  = fp[(size_t)4*NS];
            const float f5  = fp[(size_t)5*NS],  f6  = fp[(size_t)6*NS];
            const float f7  = fp[(size_t)7*NS],  f8  = fp[(size_t)8*NS];
            const float f9  = fp[(size_t)9*NS],  f10 = fp[(size_t)10*NS];
            const float f11 = fp[(size_t)11*NS], f12 = fp[(size_t)12*NS];

            float4 a = vreg[m];

            const float4 zm  = zreg[m];
            const float4 zm1 = (m == 3) ? st0 : zreg[(m+1)&3];
            const float4 zm2 = (m == 2) ? st0 : ((m == 3) ? st1 : zreg[(m+2)&3]);
            a.x = fmaf(f0,  zm.x,  a.x); a.y = fmaf(f0,  zm.y,  a.y);
            a.z = fmaf(f0,  zm.z,  a.z); a.w = fmaf(f0,  zm.w,  a.w);
            a.x = fmaf(f11, zm1.x, a.x); a.y = fmaf(f11, zm1.y, a.y);
            a.z = fmaf(f11, zm1.z, a.z); a.w = fmaf(f11, zm1.w, a.w);
            a.x = fmaf(f12, zm2.x, a.x); a.y = fmaf(f12, zm2.y, a.y);
            a.z = fmaf(f12, zm2.z, a.z); a.w = fmaf(f12, zm2.w, a.w);

            const float fs[10] = {f1,f2,f3,f4,f5,f6,f7,f8,f9,f10};
            const int offs[10] = {1,2,4,8,16,32,64,128,256,512};
#pragma unroll
            for (int li = 0; li < 10; li++) {
                const int j = (i + offs[li]) & (NS-1);
                const float fl = fs[li];
                float4 z = Zr[j];
                a.x = fmaf(fl, z.x, a.x); a.y = fmaf(fl, z.y, a.y);
                a.z = fmaf(fl, z.z, a.z); a.w = fmaf(fl, z.w, a.w);
            }

            Zw[i] = a;
            zreg[m] = a;
        }
        __syncthreads();
    }

#pragma unroll
    for (int m = 0; m < 4; m++) {
        const int i = t + 1024*m;
        *(float4*)(outZ + ((size_t)b*NS + i)*64 + c0) = zreg[m];
    }
}

// ---------------------------------------------------------------------------
extern "C" void kernel_launch(void* const* d_in, const int* in_sizes, int n_in,
                              void* d_out, int out_size) {
    const int*   tok  = (const int*)  d_in[0];
    const float* emb  = (const float*)d_in[1];
    const float* fW1  = (const float*)d_in[2];
    const float* fb1  = (const float*)d_in[3];
    const float* fW2  = (const float*)d_in[4];
    const float* fb2  = (const float*)d_in[5];
    const float* vW1  = (const float*)d_in[6];
    const float* vb1  = (const float*)d_in[7];
    const float* vW2  = (const float*)d_in[8];
    const float* vb2  = (const float*)d_in[9];
    const float* finW = (const float*)d_in[10];
    const float* finb = (const float*)d_in[11];
    float* out = (float*)d_out;

    const int tables_smem = (1024 + 8192 + 2176 + 8192) * 4;   // 78336
    const int chord_smem  = NS * 2 * 16;                       // 131072
    cudaFuncSetAttribute(tables_kernel,    cudaFuncAttributeMaxDynamicSharedMemorySize, tables_smem);
    cudaFuncSetAttribute(chord_all_kernel, cudaFuncAttributeMaxDynamicSharedMemorySize, chord_smem);

    cudaMemsetAsync(out, 0, NB*NCLS*sizeof(float));

    dim3 tgrid(32, 14);
    tables_kernel<<<tgrid, 256, tables_smem>>>(emb, fW1, fb1, fW2, fb2,
                                               vW1, vb1, vW2, vb2);

    fgather_logits_kernel<<<3328 + 512, 256>>>(tok, finW, finb, out);

    float* zdst;
    if (out_size >= NB*NCLS + ROWS*ND) zdst = out + NB*NCLS;
    else cudaGetSymbolAddress((void**)&zdst, g_Zdump);
    chord_all_kernel<<<NB*16, 1024, chord_smem>>>(tok, zdst);
}